// round 15
// baseline (speedup 1.0000x reference)
#include <cuda_runtime.h>
#include <cstdint>

// FeatureSim: attn[b,i,j] = softmax_j( masked(-sum_f |x[b,i,f]-x[b,j,f]| * w[f]) )
// B=8, N=1024, D=64, NF=11.
// Kernel 1 (v2): coalesced transpose x[:,:,:11] -> SoA planes g_xt[f][b*N+row]:
//   thread t does one fully-coalesced float4 load of x; threads with q<3 scatter.
// Kernel 2: 128 threads x 8 j-cols, R=4 rows/CTA, launch_bounds(128,6):
//   e[] fully register-resident (no smem staging), SHFL tail halved, 4-warp
//   barrier, 2048 fine-grained CTAs. f-major software-pipelined inner loop.
//   Softmax without max-pass (valid scores in (-1,0], exp-safe; invalid -> 0).
// (Resubmission — round 14 died on container-acquisition infra, source never ran.)

static constexpr int B_ = 8;
static constexpr int N_ = 1024;
static constexpr int D_ = 64;
static constexpr int NF = 11;
static constexpr int BN = B_ * N_;   // 8192
static constexpr int R = 4;
#define BDIM 128
#define NW   (BDIM / 32)             // 4 warps

__device__ float g_xt[NF * BN];   // 352 KB scratch, feature-major (SoA)

__global__ void transpose_kernel(const float* __restrict__ x) {
    int t = blockIdx.x * blockDim.x + threadIdx.x;   // 0 .. BN*16-1
    int row = t >> 4;
    int q   = t & 15;                                // which float4 of the 64-float row
    if (q < 3) {
        float4 v = reinterpret_cast<const float4*>(x)[t];   // fully coalesced
        int f0 = q * 4;
        g_xt[(f0 + 0) * BN + row] = v.x;
        g_xt[(f0 + 1) * BN + row] = v.y;
        g_xt[(f0 + 2) * BN + row] = v.z;
        if (q < 2)                      // f = 11 not needed (NF = 11 -> f 0..10)
            g_xt[(f0 + 3) * BN + row] = v.w;
    }
}

__global__ __launch_bounds__(BDIM, 6) void featuresim_kernel(
    const int*   __restrict__ xlen,     // (B,)
    const float* __restrict__ fimp,     // (NF,)
    float*       __restrict__ out)      // (B,N,N)
{
    const int b    = blockIdx.y;
    const int i0   = blockIdx.x * R;
    const int tid  = threadIdx.x;
    const int lane = tid & 31;
    const int wid  = tid >> 5;

    const int base = b * N_;
    const int len  = xlen[b];
    const int j0   = tid * 8;

    __shared__ float reds[R][NW];

    const float* pj = g_xt + base + j0;   // this thread's 8-col j base
    const float* pi = g_xt + base + i0;   // CTA's 4 i-rows base (uniform)

    float w[NF];
#pragma unroll
    for (int f = 0; f < NF; f++) w[f] = __ldg(fimp + f);

    float acc[R][8];
#pragma unroll
    for (int r = 0; r < R; r++)
#pragma unroll
        for (int c = 0; c < 8; c++) acc[r][c] = 0.f;

    // Software-pipelined f-major loop: prefetch f+1's loads during f's 32 FMAs.
    float4 xjA_n = *reinterpret_cast<const float4*>(pj);
    float4 xjB_n = *reinterpret_cast<const float4*>(pj + 4);
    float4 xi_n  = *reinterpret_cast<const float4*>(pi);

#pragma unroll
    for (int f = 0; f < NF; f++) {
        const float4 xjA = xjA_n;
        const float4 xjB = xjB_n;
        const float4 xi  = xi_n;
        if (f + 1 < NF) {
            xjA_n = *reinterpret_cast<const float4*>(pj + (f + 1) * BN);
            xjB_n = *reinterpret_cast<const float4*>(pj + (f + 1) * BN + 4);
            xi_n  = *reinterpret_cast<const float4*>(pi + (f + 1) * BN);
        }
        const float wf = w[f];
        const float xjv[8] = { xjA.x, xjA.y, xjA.z, xjA.w,
                               xjB.x, xjB.y, xjB.z, xjB.w };
        const float xiv[R] = { xi.x, xi.y, xi.z, xi.w };
#pragma unroll
        for (int r = 0; r < R; r++) {
            const float xv = xiv[r];
#pragma unroll
            for (int c = 0; c < 8; c++)
                acc[r][c] = fmaf(fabsf(xjv[c] - xv), wf, acc[r][c]);
        }
    }

    bool valid[8];
#pragma unroll
    for (int c = 0; c < 8; c++) valid[c] = (j0 + c) < len;

    float e[R][8];
    float inv[R];
#pragma unroll
    for (int r = 0; r < R; r++) {
        float ps = 0.f;
#pragma unroll
        for (int c = 0; c < 8; c++) {
            const float s = acc[r][c];
            const float t = (s < 1.0f) ? -s : 0.0f;
            // No max-pass: valid scores in (-1,0]; invalid -> exp(-1e9) == 0.
            const float ev = __expf(valid[c] ? t : -1.0e9f);
            e[r][c] = ev;
            ps += ev;
        }
#pragma unroll
        for (int o = 16; o > 0; o >>= 1)
            ps += __shfl_xor_sync(0xFFFFFFFFu, ps, o);
        if (lane == 0) reds[r][wid] = ps;
    }
    __syncthreads();

#pragma unroll
    for (int r = 0; r < R; r++) {
        float t = reds[r][0] + reds[r][1] + reds[r][2] + reds[r][3];
        inv[r] = 1.0f / t;
    }

#pragma unroll
    for (int r = 0; r < R; r++) {
        float4 oA, oB;
        oA.x = e[r][0] * inv[r];  oA.y = e[r][1] * inv[r];
        oA.z = e[r][2] * inv[r];  oA.w = e[r][3] * inv[r];
        oB.x = e[r][4] * inv[r];  oB.y = e[r][5] * inv[r];
        oB.z = e[r][6] * inv[r];  oB.w = e[r][7] * inv[r];
        float* orow = out + ((size_t)(b * N_ + i0 + r)) * N_ + j0;
        *reinterpret_cast<float4*>(orow)     = oA;
        *reinterpret_cast<float4*>(orow + 4) = oB;
    }
}

extern "C" void kernel_launch(void* const* d_in, const int* in_sizes, int n_in,
                              void* d_out, int out_size)
{
    const float* x    = (const float*)d_in[0];
    const int*   xlen = (const int*)d_in[1];
    const float* fimp = (const float*)d_in[2];
    float*       out  = (float*)d_out;

    transpose_kernel<<<(BN * 16) / 256, 256>>>(x);
    dim3 grid(N_ / R, B_);
    featuresim_kernel<<<grid, BDIM>>>(xlen, fimp, out);
}